// round 11
// baseline (speedup 1.0000x reference)
#include <cuda_runtime.h>
#include <cuda_bf16.h>
#include <math.h>
#include <stdint.h>

#define B_ 1024
#define L_ 1024
#define T_ 32
#define H_ 2048
#define K_ 64
#define O_ 256

// ---------------- static device scratch (allocation-guard safe) ------------
__device__ float g_hidden[(size_t)T_ * B_ * H_];          // 256 MB [t][b][h]
__device__ float g_sparse[(size_t)T_ * B_ * K_];          // 8 MB
__device__ __nv_bfloat16 g_xh[(size_t)B_ * L_];           // [b][l] hi
__device__ __nv_bfloat16 g_xl[(size_t)B_ * L_];           // [b][l] lo
__device__ __nv_bfloat16 g_wh[(size_t)T_ * L_ * H_];      // [t][l][h] hi (k-major)
__device__ __nv_bfloat16 g_wl[(size_t)T_ * L_ * H_];      // [t][l][h] lo

// ---------------- helpers ---------------------------------------------------
__device__ __forceinline__ uint32_t smem_u32(const void* p) {
    uint32_t a;
    asm("{ .reg .u64 t; cvta.to.shared.u64 t, %1; cvt.u32.u64 %0, t; }"
        : "=r"(a) : "l"(p));
    return a;
}
__device__ __forceinline__ void cpa16(uint32_t s, const void* g) {
    asm volatile("cp.async.cg.shared.global [%0], [%1], 16;" :: "r"(s), "l"(g));
}
#define CPA_COMMIT() asm volatile("cp.async.commit_group;" ::: "memory")
#define CPA_WAIT(n)  asm volatile("cp.async.wait_group %0;" :: "n"(n) : "memory")

#define LDSM4(r0, r1, r2, r3, a)                                               \
    asm volatile("ldmatrix.sync.aligned.m8n8.x4.shared.b16 {%0,%1,%2,%3},[%4];"\
                 : "=r"(r0), "=r"(r1), "=r"(r2), "=r"(r3) : "r"(a))
#define LDSM4T(r0, r1, r2, r3, a)                                              \
    asm volatile("ldmatrix.sync.aligned.m8n8.x4.trans.shared.b16 "             \
                 "{%0,%1,%2,%3},[%4];"                                         \
                 : "=r"(r0), "=r"(r1), "=r"(r2), "=r"(r3) : "r"(a))
#define MMA16816(c, a0, a1, a2, a3, b0, b1)                                    \
    asm volatile("mma.sync.aligned.m16n8k16.row.col.f32.bf16.bf16.f32 "        \
                 "{%0,%1,%2,%3},{%4,%5,%6,%7},{%8,%9},{%0,%1,%2,%3};"          \
                 : "+f"((c)[0]), "+f"((c)[1]), "+f"((c)[2]), "+f"((c)[3])      \
                 : "r"(a0), "r"(a1), "r"(a2), "r"(a3), "r"(b0), "r"(b1))

// ---------------- conversion: f32 -> (hi, lo) bf16 --------------------------
__global__ __launch_bounds__(256) void conv_split(const float* __restrict__ src,
                                                  __nv_bfloat16* __restrict__ dh,
                                                  __nv_bfloat16* __restrict__ dl) {
    size_t i = (size_t)blockIdx.x * 256 + threadIdx.x;   // float4 index
    float4 v = ((const float4*)src)[i];
    float vv[4] = {v.x, v.y, v.z, v.w};
    __nv_bfloat16 hi[4], lo[4];
    #pragma unroll
    for (int j = 0; j < 4; j++) {
        hi[j] = __float2bfloat16(vv[j]);
        lo[j] = __float2bfloat16(vv[j] - __bfloat162float(hi[j]));
    }
    ((uint2*)dh)[i] = *(uint2*)hi;
    ((uint2*)dl)[i] = *(uint2*)lo;
}

// ---------------- HMMA GEMM: hidden[t] = x @ Wt[t] --------------------------
// block tile 128m x 256n, BK=32; 8 warps 2m x 4n -> warp tile 64x64
#define BM 128
#define BN 256
#define BKC 32
#define NCH (L_ / BKC)          // 32 chunks

#define A_STRIDE 40             // halves per A row (80 B)
#define B_STRIDE 264            // halves per B k-row (528 B; 132 words = 4 mod 32)
#define AH_OFF 0
#define AL_OFF (128 * A_STRIDE)                  // 5120
#define BH_OFF (2 * 128 * A_STRIDE)              // 10240
#define BL_OFF (BH_OFF + 32 * B_STRIDE)          // 18688
#define STAGE_H (BL_OFF + 32 * B_STRIDE)         // 27136 halves = 54272 B
#define GEMM_SMEM (2 * STAGE_H * 2)              // 108544 B

__global__ __launch_bounds__(256) void gemm_mma() {
    extern __shared__ __align__(16) __nv_bfloat16 sm[];
    const uint32_t sbase = smem_u32(sm);
    const int tid  = threadIdx.x;
    const int wid  = tid >> 5;
    const int lane = tid & 31;
    const int t  = blockIdx.z;
    const int m0 = blockIdx.x * BM;
    const int n0 = blockIdx.y * BN;
    const int wm = (wid & 1) * 64;      // warp m offset
    const int wn = (wid >> 1) * 64;     // warp n offset

    const __nv_bfloat16* Wh = g_wh + (size_t)t * L_ * H_;
    const __nv_bfloat16* Wl = g_wl + (size_t)t * L_ * H_;

    // per-thread prefetch coordinates
    const int a_row0 = tid >> 2, a_kc = (tid & 3) * 8;    // A: 512 uint4/split
    const int b_kr0  = tid >> 5, b_nc = (tid & 31) * 8;   // B: 1024 uint4/split

    auto prefetch = [&](int c) {
        const int k0 = c * BKC;
        const uint32_t st = sbase + (uint32_t)((c & 1) * STAGE_H) * 2;
        #pragma unroll
        for (int i = 0; i < 2; i++) {
            int row = a_row0 + i * 64;
            size_t g = (size_t)(m0 + row) * L_ + k0 + a_kc;
            uint32_t so = (uint32_t)(row * A_STRIDE + a_kc) * 2;
            cpa16(st + AH_OFF * 2 + so, g_xh + g);
            cpa16(st + AL_OFF * 2 + so, g_xl + g);
        }
        #pragma unroll
        for (int i = 0; i < 4; i++) {
            int kr = b_kr0 + i * 8;
            size_t g = (size_t)(k0 + kr) * H_ + n0 + b_nc;
            uint32_t so = (uint32_t)(kr * B_STRIDE + b_nc) * 2;
            cpa16(st + BH_OFF * 2 + so, Wh + g);
            cpa16(st + BL_OFF * 2 + so, Wl + g);
        }
    };

    float acc[4][8][4];
    #pragma unroll
    for (int mi = 0; mi < 4; mi++)
        #pragma unroll
        for (int ni = 0; ni < 8; ni++)
            #pragma unroll
            for (int j = 0; j < 4; j++) acc[mi][ni][j] = 0.0f;

    prefetch(0); CPA_COMMIT();

    const int a_lm_row = wm + (lane & 15);            // + mi*16
    const int a_lm_col = (lane >> 4) * 8;             // + ks*16
    const int b_lm_row = lane & 15;                   // + ks*16
    const int b_lm_col = wn + ((lane >> 4) * 8);      // + nb*16

    for (int c = 0; c < NCH; c++) {
        if (c + 1 < NCH) { prefetch(c + 1); CPA_COMMIT(); CPA_WAIT(1); }
        else             { CPA_WAIT(0); }
        __syncthreads();

        const uint32_t st = sbase + (uint32_t)((c & 1) * STAGE_H) * 2;
        #pragma unroll
        for (int ks = 0; ks < 2; ks++) {
            uint32_t a[4][4], bh[4][4], bl[4][4];
            // load Ah, Bh, Bl fragments
            #pragma unroll
            for (int mi = 0; mi < 4; mi++) {
                uint32_t ad = st + AH_OFF * 2 +
                    (uint32_t)((a_lm_row + mi * 16) * A_STRIDE + a_lm_col + ks * 16) * 2;
                LDSM4(a[mi][0], a[mi][1], a[mi][2], a[mi][3], ad);
            }
            #pragma unroll
            for (int nb = 0; nb < 4; nb++) {
                uint32_t bd = st + BH_OFF * 2 +
                    (uint32_t)((b_lm_row + ks * 16) * B_STRIDE + b_lm_col + nb * 16) * 2;
                LDSM4T(bh[nb][0], bh[nb][1], bh[nb][2], bh[nb][3], bd);
            }
            #pragma unroll
            for (int nb = 0; nb < 4; nb++) {
                uint32_t bd = st + BL_OFF * 2 +
                    (uint32_t)((b_lm_row + ks * 16) * B_STRIDE + b_lm_col + nb * 16) * 2;
                LDSM4T(bl[nb][0], bl[nb][1], bl[nb][2], bl[nb][3], bd);
            }
            // pass 0: Ah x Bh
            #pragma unroll
            for (int mi = 0; mi < 4; mi++)
                #pragma unroll
                for (int ni = 0; ni < 8; ni++)
                    MMA16816(acc[mi][ni], a[mi][0], a[mi][1], a[mi][2], a[mi][3],
                             bh[ni >> 1][(ni & 1) * 2], bh[ni >> 1][(ni & 1) * 2 + 1]);
            // pass 1: Ah x Bl (Ah held)
            #pragma unroll
            for (int mi = 0; mi < 4; mi++)
                #pragma unroll
                for (int ni = 0; ni < 8; ni++)
                    MMA16816(acc[mi][ni], a[mi][0], a[mi][1], a[mi][2], a[mi][3],
                             bl[ni >> 1][(ni & 1) * 2], bl[ni >> 1][(ni & 1) * 2 + 1]);
            // pass 2: Al x Bh (Bh held; reload A regs with Al)
            #pragma unroll
            for (int mi = 0; mi < 4; mi++) {
                uint32_t ad = st + AL_OFF * 2 +
                    (uint32_t)((a_lm_row + mi * 16) * A_STRIDE + a_lm_col + ks * 16) * 2;
                LDSM4(a[mi][0], a[mi][1], a[mi][2], a[mi][3], ad);
            }
            #pragma unroll
            for (int mi = 0; mi < 4; mi++)
                #pragma unroll
                for (int ni = 0; ni < 8; ni++)
                    MMA16816(acc[mi][ni], a[mi][0], a[mi][1], a[mi][2], a[mi][3],
                             bh[ni >> 1][(ni & 1) * 2], bh[ni >> 1][(ni & 1) * 2 + 1]);
        }
        __syncthreads();
    }

    float* C = g_hidden + (size_t)t * B_ * H_;
    #pragma unroll
    for (int mi = 0; mi < 4; mi++) {
        int row = m0 + wm + mi * 16 + (lane >> 2);
        #pragma unroll
        for (int ni = 0; ni < 8; ni++) {
            int col = n0 + wn + ni * 8 + (lane & 3) * 2;
            *(float2*)(C + (size_t)row * H_ + col) =
                make_float2(acc[mi][ni][0], acc[mi][ni][1]);
            *(float2*)(C + (size_t)(row + 8) * H_ + col) =
                make_float2(acc[mi][ni][2], acc[mi][ni][3]);
        }
    }
}

// ---------------- top-64 via 2-pass radix select + rank selection -----------
__global__ __launch_bounds__(256) void topk_kernel() {
    __shared__ uint32_t hist[256];
    __shared__ uint32_t wtot[8];
    __shared__ uint32_t cand_v[256];
    __shared__ uint32_t cand_i[256];
    __shared__ uint32_t s_b1, s_c1, s_pfx, s_cnt;

    const int tid = threadIdx.x;
    const int lane = tid & 31;
    const int wrp  = tid >> 5;
    const int b = blockIdx.x;
    const int t = blockIdx.y;
    const float* row = g_hidden + ((size_t)t * B_ + b) * H_;

    uint32_t v[8];
    #pragma unroll
    for (int i = 0; i < 2; i++) {
        float4 f4 = ((const float4*)row)[tid + i * 256];
        float ff[4] = {f4.x, f4.y, f4.z, f4.w};
        #pragma unroll
        for (int j = 0; j < 4; j++) {
            uint32_t u = __float_as_uint(ff[j]);
            v[i * 4 + j] = (u & 0x80000000u) ? ~u : (u | 0x80000000u);
        }
    }

    // ---- pass 1: histogram on bits [24,32) ----
    hist[tid] = 0;
    __syncthreads();
    #pragma unroll
    for (int i = 0; i < 8; i++) atomicAdd(&hist[v[i] >> 24], 1u);
    __syncthreads();
    {
        uint32_t h = hist[tid];
        uint32_t s = h;
        #pragma unroll
        for (int off = 1; off < 32; off <<= 1) {
            uint32_t tmp = __shfl_down_sync(0xffffffffu, s, off);
            if (lane + off < 32) s += tmp;
        }
        if (lane == 0) wtot[wrp] = s;
        __syncthreads();
        uint32_t later = 0;
        for (int w = wrp + 1; w < 8; w++) later += wtot[w];
        uint32_t scn = s + later;
        uint32_t above = scn - h;
        if (scn >= K_ && above < K_) { s_b1 = (uint32_t)tid; s_c1 = above; }
    }
    __syncthreads();
    const uint32_t b1 = s_b1;
    const uint32_t need2 = K_ - s_c1;

    // ---- pass 2: histogram on bits [16,24) within bucket b1 ----
    hist[tid] = 0;
    __syncthreads();
    #pragma unroll
    for (int i = 0; i < 8; i++)
        if ((v[i] >> 24) == b1) atomicAdd(&hist[(v[i] >> 16) & 0xFFu], 1u);
    __syncthreads();
    {
        uint32_t h = hist[tid];
        uint32_t s = h;
        #pragma unroll
        for (int off = 1; off < 32; off <<= 1) {
            uint32_t tmp = __shfl_down_sync(0xffffffffu, s, off);
            if (lane + off < 32) s += tmp;
        }
        if (lane == 0) wtot[wrp] = s;
        if (tid == 0) s_cnt = 0;
        __syncthreads();
        uint32_t later = 0;
        for (int w = wrp + 1; w < 8; w++) later += wtot[w];
        uint32_t scn = s + later;
        uint32_t above = scn - h;
        if (scn >= need2 && above < need2)
            s_pfx = (b1 << 8) | (uint32_t)tid;
    }
    __syncthreads();
    const uint32_t pfx = s_pfx;

    #pragma unroll
    for (int i = 0; i < 8; i++) {
        if ((v[i] >> 16) >= pfx) {
            uint32_t p = atomicAdd(&s_cnt, 1u);
            if (p < 256) {
                cand_v[p] = v[i];
                cand_i[p] = (uint32_t)((tid + (i >> 2) * 256) * 4 + (i & 3));
            }
        }
    }
    __syncthreads();

    const int cnt = (int)min(s_cnt, 256u);
    if (tid < cnt) {
        const uint32_t mv = cand_v[tid];
        const uint32_t mi = cand_i[tid];
        int r = 0;
        for (int k = 0; k < cnt; k++) {
            uint32_t cv = cand_v[k];
            r += (cv > mv) || (cv == mv && cand_i[k] < mi);
        }
        if (r < K_) {
            uint32_t orig = (mv & 0x80000000u) ? (mv & 0x7FFFFFFFu) : ~mv;
            g_sparse[((size_t)t * B_ + b) * K_ + r] = __uint_as_float(orig);
        }
    }
}

// ---------------- dense + GELU + LayerNorm (16 rows per block) ---------------
#define DB 16

__global__ __launch_bounds__(256) void dense_kernel(const float* __restrict__ dW,
                                                    const float* __restrict__ db,
                                                    const float* __restrict__ gamma,
                                                    const float* __restrict__ beta,
                                                    float* __restrict__ out) {
    __shared__ float gs[DB][K_];
    __shared__ float wred[DB][8];
    __shared__ float s_mean[DB], s_rstd[DB];

    const int bg = blockIdx.x * DB;
    const int t  = blockIdx.y;
    const int o  = threadIdx.x;
    const int wid = o >> 5, lane = o & 31;

    #pragma unroll
    for (int i = 0; i < DB * K_ / 256; i++) {
        int lin = o + i * 256;
        gs[lin >> 6][lin & 63] =
            g_sparse[((size_t)t * B_ + bg) * K_ + lin];
    }
    __syncthreads();

    const float* W = dW + (size_t)t * K_ * O_;
    float acc[DB];
    const float bias = db[t * O_ + o];
    #pragma unroll
    for (int j = 0; j < DB; j++) acc[j] = bias;

    #pragma unroll 8
    for (int k = 0; k < K_; k++) {
        float w = W[k * O_ + o];
        #pragma unroll
        for (int j = 0; j < DB; j++) acc[j] = fmaf(gs[j][k], w, acc[j]);
    }

    float y[DB];
    #pragma unroll
    for (int j = 0; j < DB; j++)
        y[j] = 0.5f * acc[j] * (1.0f + erff(acc[j] * 0.70710678118654752f));

    #pragma unroll
    for (int j = 0; j < DB; j++) {
        float v = y[j];
        #pragma unroll
        for (int off = 16; off; off >>= 1) v += __shfl_xor_sync(0xffffffffu, v, off);
        if (lane == 0) wred[j][wid] = v;
    }
    __syncthreads();
    if (o < DB) {
        float s = 0.f;
        #pragma unroll
        for (int w = 0; w < 8; w++) s += wred[o][w];
        s_mean[o] = s * (1.0f / O_);
    }
    __syncthreads();
    #pragma unroll
    for (int j = 0; j < DB; j++) {
        float d = y[j] - s_mean[j];
        float v = d * d;
        #pragma unroll
        for (int off = 16; off; off >>= 1) v += __shfl_xor_sync(0xffffffffu, v, off);
        if (lane == 0) wred[j][wid] = v;
    }
    __syncthreads();
    if (o < DB) {
        float s = 0.f;
        #pragma unroll
        for (int w = 0; w < 8; w++) s += wred[o][w];
        s_rstd[o] = rsqrtf(s * (1.0f / O_) + 1e-6f);
    }
    __syncthreads();

    const float gm = gamma[t * O_ + o];
    const float bt = beta[t * O_ + o];
    #pragma unroll
    for (int j = 0; j < DB; j++) {
        out[((size_t)(bg + j) * T_ + t) * O_ + o] =
            (y[j] - s_mean[j]) * s_rstd[j] * gm + bt;
    }
}

// ---------------------------------------------------------------------------
extern "C" void kernel_launch(void* const* d_in, const int* in_sizes, int n_in,
                              void* d_out, int out_size) {
    const float* x     = (const float*)d_in[0];
    const float* Wt    = (const float*)d_in[1];
    const float* dW    = (const float*)d_in[2];
    const float* db    = (const float*)d_in[3];
    const float* gamma = (const float*)d_in[4];
    const float* beta  = (const float*)d_in[5];
    float* out = (float*)d_out;

    __nv_bfloat16 *xh, *xl, *wh, *wl;
    cudaGetSymbolAddress((void**)&xh, g_xh);
    cudaGetSymbolAddress((void**)&xl, g_xl);
    cudaGetSymbolAddress((void**)&wh, g_wh);
    cudaGetSymbolAddress((void**)&wl, g_wl);

    cudaFuncSetAttribute(gemm_mma, cudaFuncAttributeMaxDynamicSharedMemorySize,
                         GEMM_SMEM);

    conv_split<<<(B_ * L_ / 4) / 256, 256>>>(x, xh, xl);
    conv_split<<<((size_t)T_ * L_ * H_ / 4) / 256, 256>>>(Wt, wh, wl);
    gemm_mma<<<dim3(B_ / BM, H_ / BN, T_), 256, GEMM_SMEM>>>();
    topk_kernel<<<dim3(B_, T_), 256>>>();
    dense_kernel<<<dim3(B_ / DB, T_), 256>>>(dW, db, gamma, beta, out);
}